// round 1
// baseline (speedup 1.0000x reference)
#include <cuda_runtime.h>
#include <math.h>

#define TT 2048      // tokens
#define HH 2048      // hidden
#define II 1024      // moe intermediate
#define EE 32        // routed experts
#define TOPK 4
#define NROUTED (TT*TOPK)       // 8192
#define NPAIRS  (NROUTED + TT)  // 10240 (routed pairs + shared-expert rows)

// ---------------- device scratch (static: no allocation allowed) ----------------
__device__ int   g_counts[EE];
__device__ int   g_cursor[EE];
__device__ int   g_offsets[EE];
__device__ int   g_topk_idx[NROUTED];
__device__ float g_topk_w[NROUTED];
__device__ int   g_pair_token[NROUTED];   // pos -> token
__device__ int   g_pair_pos[NROUTED];     // t*4+j -> pos
__device__ float g_act[(size_t)NPAIRS * II];       // ~42 MB
__device__ float g_pairout[(size_t)NPAIRS * HH];   // ~84 MB

// ---------------- misc small kernels ----------------
__global__ void zero_kernel() {
    int i = threadIdx.x;
    if (i < EE) { g_counts[i] = 0; g_cursor[i] = 0; }
}

__global__ void offsets_kernel() {
    if (threadIdx.x == 0) {
        int s = 0;
        for (int e = 0; e < EE; ++e) { g_offsets[e] = s; s += g_counts[e]; }
    }
}

__global__ void scatter_kernel() {
    int t = blockIdx.x * blockDim.x + threadIdx.x;
    if (t >= TT) return;
    #pragma unroll
    for (int j = 0; j < TOPK; ++j) {
        int e = g_topk_idx[t*TOPK + j];
        int pos = g_offsets[e] + atomicAdd(&g_cursor[e], 1);
        g_pair_token[pos] = t;
        g_pair_pos[t*TOPK + j] = pos;
    }
}

// ---------------- gate + routing: 4 tokens per block ----------------
__global__ __launch_bounds__(256) void gate_kernel(
        const float* __restrict__ x,
        const float* __restrict__ gw,
        const float* __restrict__ bias)
{
    __shared__ float xs[4][HH];
    __shared__ float logits_s[4][EE];
    __shared__ float bias_s[EE];

    int tid = threadIdx.x;
    int t0  = blockIdx.x * 4;

    // load 4 token rows (4*2048 floats = 2048 float4)
    const float4* xg  = (const float4*)(x + (size_t)t0 * HH);
    float4*       xs4 = (float4*)&xs[0][0];
    #pragma unroll
    for (int i = 0; i < 8; ++i) xs4[tid + i*256] = xg[tid + i*256];
    if (tid < EE) bias_s[tid] = bias[tid];
    __syncthreads();

    int warp = tid >> 5, lane = tid & 31;

    // 8 warps x 4 experts each, 4 tokens per dot
    #pragma unroll
    for (int ei = 0; ei < 4; ++ei) {
        int e = warp*4 + ei;
        const float* gr = gw + (size_t)e * HH;
        float a0=0.f, a1=0.f, a2=0.f, a3=0.f;
        for (int h = lane; h < HH; h += 32) {
            float g = gr[h];
            a0 = fmaf(g, xs[0][h], a0);
            a1 = fmaf(g, xs[1][h], a1);
            a2 = fmaf(g, xs[2][h], a2);
            a3 = fmaf(g, xs[3][h], a3);
        }
        #pragma unroll
        for (int off = 16; off; off >>= 1) {
            a0 += __shfl_xor_sync(0xffffffffu, a0, off);
            a1 += __shfl_xor_sync(0xffffffffu, a1, off);
            a2 += __shfl_xor_sync(0xffffffffu, a2, off);
            a3 += __shfl_xor_sync(0xffffffffu, a3, off);
        }
        if (lane == 0) {
            logits_s[0][e] = a0; logits_s[1][e] = a1;
            logits_s[2][e] = a2; logits_s[3][e] = a3;
        }
    }
    __syncthreads();

    // warps 0..3: routing for token t0+warp, lane = expert
    if (warp < 4) {
        int t = t0 + warp;
        float logit = logits_s[warp][lane];
        float s   = 1.f / (1.f + expf(-logit));     // sigmoid score
        float sfc = s + bias_s[lane];               // biased score for choice

        // --- group score: sum of top-2 within each 8-lane group ---
        float m1 = sfc, m2 = -INFINITY;
        #pragma unroll
        for (int off = 4; off >= 1; off >>= 1) {    // xor 4,2,1 stays inside 8-lane group
            float o1 = __shfl_xor_sync(0xffffffffu, m1, off);
            float o2 = __shfl_xor_sync(0xffffffffu, m2, off);
            float hi = fmaxf(m1, o1);
            float lo = fmaxf(fminf(m1, o1), fmaxf(m2, o2));
            m1 = hi; m2 = lo;
        }
        float gs = m1 + m2;
        float gv[4];
        gv[0] = __shfl_sync(0xffffffffu, gs, 0);
        gv[1] = __shfl_sync(0xffffffffu, gs, 8);
        gv[2] = __shfl_sync(0xffffffffu, gs, 16);
        gv[3] = __shfl_sync(0xffffffffu, gs, 24);

        // top-2 groups (strict >, so ties keep lower index == lax.top_k)
        int b1 = 0; float v1 = gv[0];
        #pragma unroll
        for (int gg = 1; gg < 4; ++gg) if (gv[gg] > v1) { v1 = gv[gg]; b1 = gg; }
        int b2 = -1; float v2 = -INFINITY;
        #pragma unroll
        for (int gg = 0; gg < 4; ++gg) {
            if (gg == b1) continue;
            if (gv[gg] > v2) { v2 = gv[gg]; b2 = gg; }
        }

        int mygrp = lane >> 3;
        float val = (mygrp == b1 || mygrp == b2) ? sfc : 0.0f;  // match jnp.where(...,0.0)

        // --- top-4 experts on masked biased scores (lower-index tiebreak) ---
        int   sel_i[TOPK];
        float sel_w[TOPK];
        float cur = val;
        #pragma unroll
        for (int j = 0; j < TOPK; ++j) {
            float bv = cur; int bi = lane;
            #pragma unroll
            for (int off = 16; off >= 1; off >>= 1) {
                float ov = __shfl_xor_sync(0xffffffffu, bv, off);
                int   oi = __shfl_xor_sync(0xffffffffu, bi, off);
                if (ov > bv || (ov == bv && oi < bi)) { bv = ov; bi = oi; }
            }
            sel_i[j] = bi;
            sel_w[j] = __shfl_sync(0xffffffffu, s, bi);  // UNbiased sigmoid score
            if (lane == bi) cur = -INFINITY;
        }
        if (lane == 0) {
            float sum = sel_w[0] + sel_w[1] + sel_w[2] + sel_w[3];
            float scale = 2.5f / (sum + 1e-20f);
            #pragma unroll
            for (int j = 0; j < TOPK; ++j) {
                g_topk_idx[t*TOPK + j] = sel_i[j];
                g_topk_w[t*TOPK + j]   = sel_w[j] * scale;
                atomicAdd(&g_counts[sel_i[j]], 1);
            }
        }
    }
}

// ---------------- phase A: act = silu(X W1^T) * (X W3^T), expert-gathered ----------------
// grid: (II/64, EE+1, 32) ; block 256
__global__ __launch_bounds__(256) void phaseA_kernel(
        const float* __restrict__ x,
        const float* __restrict__ w1,
        const float* __restrict__ w3,
        const float* __restrict__ ws1,
        const float* __restrict__ ws3)
{
    const int g = blockIdx.y;
    int m_count, base_pos;
    const float *W1, *W3;
    if (g < EE) {
        m_count = g_counts[g]; base_pos = g_offsets[g];
        W1 = w1 + (size_t)g * II * HH; W3 = w3 + (size_t)g * II * HH;
    } else {
        m_count = TT; base_pos = NROUTED; W1 = ws1; W3 = ws3;
    }
    const int mtile = blockIdx.z;
    if (mtile * 64 >= m_count) return;
    const int rows = min(64, m_count - mtile * 64);
    const int n0 = blockIdx.x * 64;

    __shared__ float As [16][64];
    __shared__ float B1s[16][64];
    __shared__ float B3s[16][64];
    __shared__ int   toks[64];

    const int tid = threadIdx.x;
    if (tid < 64) {
        int r = min(tid, rows - 1);
        toks[tid] = (g < EE) ? g_pair_token[base_pos + mtile*64 + r] : (mtile*64 + tid);
    }
    __syncthreads();

    const int tx = tid & 15, ty = tid >> 4;
    float c1[4][4] = {{0}}, c3[4][4] = {{0}};

    const int lr = tid >> 2;          // 0..63
    const int lk = (tid & 3) * 4;     // 0,4,8,12
    const float* arow  = x  + (size_t)toks[lr] * HH;
    const float* b1row = W1 + (size_t)(n0 + lr) * HH;
    const float* b3row = W3 + (size_t)(n0 + lr) * HH;

    for (int k0 = 0; k0 < HH; k0 += 16) {
        float4 av  = *(const float4*)(arow  + k0 + lk);
        float4 b1v = *(const float4*)(b1row + k0 + lk);
        float4 b3v = *(const float4*)(b3row + k0 + lk);
        __syncthreads();
        As [lk+0][lr]=av.x;  As [lk+1][lr]=av.y;  As [lk+2][lr]=av.z;  As [lk+3][lr]=av.w;
        B1s[lk+0][lr]=b1v.x; B1s[lk+1][lr]=b1v.y; B1s[lk+2][lr]=b1v.z; B1s[lk+3][lr]=b1v.w;
        B3s[lk+0][lr]=b3v.x; B3s[lk+1][lr]=b3v.y; B3s[lk+2][lr]=b3v.z; B3s[lk+3][lr]=b3v.w;
        __syncthreads();
        #pragma unroll
        for (int kk = 0; kk < 16; ++kk) {
            float4 a  = *(const float4*)&As [kk][ty*4];
            float4 b1 = *(const float4*)&B1s[kk][tx*4];
            float4 b3 = *(const float4*)&B3s[kk][tx*4];
            float aa[4]  = {a.x,a.y,a.z,a.w};
            float bb1[4] = {b1.x,b1.y,b1.z,b1.w};
            float bb3[4] = {b3.x,b3.y,b3.z,b3.w};
            #pragma unroll
            for (int i = 0; i < 4; ++i)
                #pragma unroll
                for (int j = 0; j < 4; ++j) {
                    c1[i][j] = fmaf(aa[i], bb1[j], c1[i][j]);
                    c3[i][j] = fmaf(aa[i], bb3[j], c3[i][j]);
                }
        }
    }

    #pragma unroll
    for (int i = 0; i < 4; ++i) {
        int ml = ty*4 + i;
        if (ml < rows) {
            int pos = base_pos + mtile*64 + ml;
            float* dst = g_act + (size_t)pos * II + n0 + tx*4;
            #pragma unroll
            for (int j = 0; j < 4; ++j) {
                float v1 = c1[i][j];
                float sig = 1.f / (1.f + expf(-v1));
                dst[j] = v1 * sig * c3[i][j];
            }
        }
    }
}

// ---------------- phase B: y = act W2^T per pair ----------------
// grid: (HH/64, EE+1, 32) ; block 256
__global__ __launch_bounds__(256) void phaseB_kernel(
        const float* __restrict__ w2,
        const float* __restrict__ ws2)
{
    const int g = blockIdx.y;
    int m_count, base_pos;
    const float* W2;
    if (g < EE) {
        m_count = g_counts[g]; base_pos = g_offsets[g];
        W2 = w2 + (size_t)g * HH * II;
    } else {
        m_count = TT; base_pos = NROUTED; W2 = ws2;
    }
    const int mtile = blockIdx.z;
    if (mtile * 64 >= m_count) return;
    const int rows = min(64, m_count - mtile * 64);
    const int n0 = blockIdx.x * 64;

    __shared__ float As[16][64];
    __shared__ float Bs[16][64];

    const int tid = threadIdx.x;
    const int tx = tid & 15, ty = tid >> 4;
    float c[4][4] = {{0}};

    const int lr = tid >> 2;
    const int lk = (tid & 3) * 4;
    const int apos = base_pos + mtile*64 + min(lr, rows - 1);
    const float* arow = g_act + (size_t)apos * II;
    const float* brow = W2 + (size_t)(n0 + lr) * II;

    for (int k0 = 0; k0 < II; k0 += 16) {
        float4 av = *(const float4*)(arow + k0 + lk);
        float4 bv = *(const float4*)(brow + k0 + lk);
        __syncthreads();
        As[lk+0][lr]=av.x; As[lk+1][lr]=av.y; As[lk+2][lr]=av.z; As[lk+3][lr]=av.w;
        Bs[lk+0][lr]=bv.x; Bs[lk+1][lr]=bv.y; Bs[lk+2][lr]=bv.z; Bs[lk+3][lr]=bv.w;
        __syncthreads();
        #pragma unroll
        for (int kk = 0; kk < 16; ++kk) {
            float4 a = *(const float4*)&As[kk][ty*4];
            float4 b = *(const float4*)&Bs[kk][tx*4];
            float aa[4] = {a.x,a.y,a.z,a.w};
            float bb[4] = {b.x,b.y,b.z,b.w};
            #pragma unroll
            for (int i = 0; i < 4; ++i)
                #pragma unroll
                for (int j = 0; j < 4; ++j)
                    c[i][j] = fmaf(aa[i], bb[j], c[i][j]);
        }
    }

    #pragma unroll
    for (int i = 0; i < 4; ++i) {
        int ml = ty*4 + i;
        if (ml < rows) {
            int pos = base_pos + mtile*64 + ml;
            float* dst = g_pairout + (size_t)pos * HH + n0 + tx*4;
            #pragma unroll
            for (int j = 0; j < 4; ++j) dst[j] = c[i][j];
        }
    }
}

// ---------------- combine: out[t] = shared[t] + sum_j w_j * pairout[pos_j] ----------------
__global__ __launch_bounds__(256) void combine_kernel(float* __restrict__ out)
{
    const int t = blockIdx.x;
    const int tid = threadIdx.x;
    __shared__ float w[TOPK];
    __shared__ int   pos[TOPK];
    if (tid < TOPK) {
        w[tid]   = g_topk_w[t*TOPK + tid];
        pos[tid] = g_pair_pos[t*TOPK + tid];
    }
    __syncthreads();
    const float4* sh = (const float4*)(g_pairout + (size_t)(NROUTED + t) * HH);
    const float4* p0 = (const float4*)(g_pairout + (size_t)pos[0] * HH);
    const float4* p1 = (const float4*)(g_pairout + (size_t)pos[1] * HH);
    const float4* p2 = (const float4*)(g_pairout + (size_t)pos[2] * HH);
    const float4* p3 = (const float4*)(g_pairout + (size_t)pos[3] * HH);
    float4* o = (float4*)(out + (size_t)t * HH);
    const float w0=w[0], w1=w[1], w2=w[2], w3=w[3];
    #pragma unroll
    for (int it = 0; it < HH/4/256; ++it) {
        int i = tid + it*256;
        float4 acc = sh[i];
        float4 v0 = p0[i], v1 = p1[i], v2 = p2[i], v3 = p3[i];
        acc.x += w0*v0.x + w1*v1.x + w2*v2.x + w3*v3.x;
        acc.y += w0*v0.y + w1*v1.y + w2*v2.y + w3*v3.y;
        acc.z += w0*v0.z + w1*v1.z + w2*v2.z + w3*v3.z;
        acc.w += w0*v0.w + w1*v1.w + w2*v2.w + w3*v3.w;
        o[i] = acc;
    }
}

// ---------------- launch ----------------
extern "C" void kernel_launch(void* const* d_in, const int* in_sizes, int n_in,
                              void* d_out, int out_size)
{
    const float* x    = (const float*)d_in[0];
    const float* gw   = (const float*)d_in[1];
    const float* bias = (const float*)d_in[2];
    const float* w1   = (const float*)d_in[3];
    const float* w3   = (const float*)d_in[4];
    const float* w2   = (const float*)d_in[5];
    const float* ws1  = (const float*)d_in[6];
    const float* ws3  = (const float*)d_in[7];
    const float* ws2  = (const float*)d_in[8];
    float* out = (float*)d_out;

    zero_kernel<<<1, 64>>>();
    gate_kernel<<<TT/4, 256>>>(x, gw, bias);
    offsets_kernel<<<1, 32>>>();
    scatter_kernel<<<TT/256, 256>>>();
    phaseA_kernel<<<dim3(II/64, EE+1, 32), 256>>>(x, w1, w3, ws1, ws3);
    phaseB_kernel<<<dim3(HH/64, EE+1, 32), 256>>>(w2, ws2);
    combine_kernel<<<TT, 256>>>(out);
}